// round 11
// baseline (speedup 1.0000x reference)
#include <cuda_runtime.h>
#include <cuda_bf16.h>
#include <cstdint>

#define SELU_SC 1.0507009873554805f
#define SELU_AL 1.6732632423543772f
#define SELU_SA (SELU_SC * SELU_AL)
#define RES_SC  0.70710678118654752440f
#define LOG2E   1.4426950408889634f
#define LN2     0.6931471805599453f
#define SC_LN2  (SELU_SC * LN2)
#define Q_SC    (0.25f * LOG2E)

__device__ __forceinline__ float selu_f(float v) {
    float p = fmaxf(v, 0.0f);
    float m = fminf(v, 0.0f);
    float e = __expf(m);
    return fmaf(SELU_SA, e, fmaf(SELU_SC, p, -SELU_SA));
}
// selu on input pre-scaled by log2e
__device__ __forceinline__ float selu_s(float s) {
    float p = fmaxf(s, 0.0f);
    float m = fminf(s, 0.0f);
    float e;
    asm("ex2.approx.ftz.f32 %0, %1;" : "=f"(e) : "f"(m));
    return fmaf(SELU_SA, e, fmaf(SC_LN2, p, -SELU_SA));
}

__constant__ int c_occ[21] = {65,66,67,68,69,70,71,72,73,74,75,76,77,
                              81,82,83,84,88,89,90,94};

__device__ float g_x[8 * 128 * 500];
__device__ float g_q[8 * 500 * 128];   // transposed: [b][t][dd]

// hi/lo bf16 split pack: hi = {b(a), b(b)}, lo = residuals
__device__ __forceinline__ void packhl(float a, float b, uint32_t& hi, uint32_t& lo) {
    __nv_bfloat16 ha = __float2bfloat16(a), hb = __float2bfloat16(b);
    float ra = a - __bfloat162float(ha);
    float rb = b - __bfloat162float(hb);
    __nv_bfloat16 la = __float2bfloat16(ra), lb = __float2bfloat16(rb);
    uint16_t ua = *reinterpret_cast<uint16_t*>(&ha);
    uint16_t ub = *reinterpret_cast<uint16_t*>(&hb);
    uint16_t va = *reinterpret_cast<uint16_t*>(&la);
    uint16_t vb = *reinterpret_cast<uint16_t*>(&lb);
    hi = ((uint32_t)ub << 16) | ua;
    lo = ((uint32_t)vb << 16) | va;
}

__device__ __forceinline__ void mma_bf16(float c[4], const uint32_t a[4],
                                         const uint32_t b[2]) {
    asm volatile(
        "mma.sync.aligned.m16n8k16.row.col.f32.bf16.bf16.f32 "
        "{%0,%1,%2,%3}, {%4,%5,%6,%7}, {%8,%9}, {%0,%1,%2,%3};"
        : "+f"(c[0]), "+f"(c[1]), "+f"(c[2]), "+f"(c[3])
        : "r"(a[0]), "r"(a[1]), "r"(a[2]), "r"(a[3]), "r"(b[0]), "r"(b[1]));
}

// ---------------------------------------------------------------------------
// Q kernel — writes Q TRANSPOSED: qout[b][t][dd]
// ---------------------------------------------------------------------------
__global__ __launch_bounds__(128)
void q_kernel(const float* __restrict__ x, const float* __restrict__ wq,
              float* __restrict__ qout) {
    const int dg = blockIdx.x;
    const int tstart = blockIdx.y * 256;
    const int b = blockIdx.z;
    const int tid = threadIdx.x;

    __shared__ float xo[21 * 264];
    __shared__ float ws[16 * 189];

    for (int i = tid; i < 21 * 264; i += 128) {
        int o = i / 264, tt = i % 264;
        int g = tstart + tt - 4;
        xo[i] = (g >= 0 && g < 500) ? x[(b * 128 + c_occ[o]) * 500 + g] : 0.0f;
    }
    for (int i = tid; i < 16 * 189; i += 128)
        ws[i] = wq[dg * 16 * 189 + i];
    __syncthreads();

    float acc0[16], acc1[16];
#pragma unroll
    for (int i = 0; i < 16; i++) { acc0[i] = 0.0f; acc1[i] = 0.0f; }

#pragma unroll 1
    for (int o = 0; o < 21; o++) {
        float xa[9], xb[9];
#pragma unroll
        for (int k = 0; k < 9; k++) {
            xa[k] = xo[o * 264 + tid + k];
            xb[k] = xo[o * 264 + tid + 128 + k];
        }
#pragma unroll
        for (int dc = 0; dc < 16; dc++) {
#pragma unroll
            for (int k = 0; k < 9; k++) {
                float w = ws[dc * 189 + o * 9 + k];
                acc0[dc] = fmaf(xa[k], w, acc0[dc]);
                acc1[dc] = fmaf(xb[k], w, acc1[dc]);
            }
        }
    }

    const int t1 = tstart + tid;
    const int t2 = t1 + 128;
#pragma unroll
    for (int g = 0; g < 4; g++) {
        if (t1 < 500) {
            float4 o1;
            o1.x = selu_f(acc0[g * 4 + 0]); o1.y = selu_f(acc0[g * 4 + 1]);
            o1.z = selu_f(acc0[g * 4 + 2]); o1.w = selu_f(acc0[g * 4 + 3]);
            *reinterpret_cast<float4*>(qout + ((size_t)(b * 500 + t1)) * 128 + dg * 16 + g * 4) = o1;
        }
        if (t2 < 500) {
            float4 o2;
            o2.x = selu_f(acc1[g * 4 + 0]); o2.y = selu_f(acc1[g * 4 + 1]);
            o2.z = selu_f(acc1[g * 4 + 2]); o2.w = selu_f(acc1[g * 4 + 3]);
            *reinterpret_cast<float4*>(qout + ((size_t)(b * 500 + t2)) * 128 + dg * 16 + g * 4) = o2;
        }
    }
}

// ---------------------------------------------------------------------------
// mma.sync fused layer kernel. grid (C=128, B=8), 256 threads (8 warps).
// Warps 0-3: K slab dd [w*32, w*32+32); warps 4-7: V slab.
// Chunk = 64 t; D[t,dd] f32 in smem (stride 268); warp-per-t epilogue.
// ---------------------------------------------------------------------------
#define DSTRIDE 268
#define SMEM_BYTES 71296

__global__ __launch_bounds__(256, 2)
void layer_mma_kernel(const float* __restrict__ xin,
                      const float* __restrict__ qT,
                      const float* __restrict__ wk,
                      const float* __restrict__ wv,
                      const float* __restrict__ wproj,
                      float* __restrict__ xout) {
    extern __shared__ char smem_raw[];
    float* Dsm = reinterpret_cast<float*>(smem_raw);            // 64 x 268
    float* xs  = reinterpret_cast<float*>(smem_raw + 68608);    // 544
    float* wps = reinterpret_cast<float*>(smem_raw + 70784);    // 128

    const int c = blockIdx.x, b = blockIdx.y, tid = threadIdx.x;
    const int wid = tid >> 5, lane = tid & 31;
    const int g = lane >> 2, tg = lane & 3;

    const float* xrow = xin + (b * 128 + c) * 500;
    for (int i = tid; i < 544; i += 256) {
        int gg = i - 4;
        xs[i] = (gg >= 0 && gg < 500) ? xrow[gg] : 0.0f;
    }
    if (tid < 128) wps[tid] = wproj[c * 128 + tid];

    // B fragments (hi/lo) for this warp's 4 n-tiles, built from gmem
    const int slab = (wid & 3) * 32;
    const int colbase = ((wid < 4) ? 0 : 128) + slab;
    const float* wsrc = ((wid < 4) ? wk : wv) + c * 1152;
    uint32_t bh[4][2], bl[4][2];
#pragma unroll
    for (int nt = 0; nt < 4; nt++) {
        const float* wr = wsrc + (slab + nt * 8 + g) * 9;
        packhl(wr[2 * tg] * LOG2E, wr[2 * tg + 1] * LOG2E, bh[nt][0], bl[nt][0]);
        if (tg == 0) {
            packhl(wr[8] * LOG2E, 0.0f, bh[nt][1], bl[nt][1]);
        } else {
            bh[nt][1] = 0u; bl[nt][1] = 0u;
        }
    }
    __syncthreads();

#pragma unroll 1
    for (int chunk = 0; chunk < 8; chunk++) {
        const int t0c = (chunk < 7) ? chunk * 64 : 436;

        // ---- MMA phase: D[t0c + 0..63][0..255] ----
#pragma unroll 1
        for (int mt = 0; mt < 4; mt++) {
            const int r0 = t0c + mt * 16 + g;
            uint32_t ah[4], al[4];
            packhl(xs[r0 + 2 * tg],      xs[r0 + 2 * tg + 1],      ah[0], al[0]);
            packhl(xs[r0 + 8 + 2 * tg],  xs[r0 + 8 + 2 * tg + 1],  ah[1], al[1]);
            packhl(xs[r0 + 2 * tg + 8],  xs[r0 + 2 * tg + 9],      ah[2], al[2]);
            packhl(xs[r0 + 8 + 2 * tg + 8], xs[r0 + 8 + 2 * tg + 9], ah[3], al[3]);

#pragma unroll
            for (int nt = 0; nt < 4; nt++) {
                float cf[4] = {0.f, 0.f, 0.f, 0.f};
                mma_bf16(cf, ah, bh[nt]);
                mma_bf16(cf, ah, bl[nt]);
                mma_bf16(cf, al, bh[nt]);
                float* d0 = &Dsm[(mt * 16 + g) * DSTRIDE + colbase + nt * 8 + 2 * tg];
                *reinterpret_cast<float2*>(d0) = make_float2(cf[0], cf[1]);
                *reinterpret_cast<float2*>(d0 + 8 * DSTRIDE) = make_float2(cf[2], cf[3]);
            }
        }
        __syncthreads();

        // ---- Epilogue: warp handles t rows wid, wid+8, ... ----
#pragma unroll 1
        for (int i = 0; i < 8; i++) {
            const int tl = wid + i * 8;
            const int tg_glob = t0c + tl;

            float4 dk = *reinterpret_cast<const float4*>(&Dsm[tl * DSTRIDE + lane * 4]);
            float4 q4 = *reinterpret_cast<const float4*>(
                qT + ((size_t)(b * 500 + tg_glob)) * 128 + lane * 4);
            float qk = q4.x * selu_s(dk.x);
            qk = fmaf(q4.y, selu_s(dk.y), qk);
            qk = fmaf(q4.z, selu_s(dk.z), qk);
            qk = fmaf(q4.w, selu_s(dk.w), qk);
            qk += __shfl_xor_sync(0xffffffffu, qk, 1);
            qk += __shfl_xor_sync(0xffffffffu, qk, 2);
            float gate = selu_s(Q_SC * qk);

            float4 dv = *reinterpret_cast<const float4*>(&Dsm[tl * DSTRIDE + 128 + lane * 4]);
            float4 w4 = *reinterpret_cast<const float4*>(&wps[lane * 4]);
            float pv = w4.x * selu_s(dv.x);
            pv = fmaf(w4.y, selu_s(dv.y), pv);
            pv = fmaf(w4.z, selu_s(dv.z), pv);
            pv = fmaf(w4.w, selu_s(dv.w), pv);

            float contrib = gate * pv;
#pragma unroll
            for (int off = 16; off; off >>= 1)
                contrib += __shfl_xor_sync(0xffffffffu, contrib, off);

            if (lane == 0) {
                xout[(b * 128 + c) * 500 + tg_glob] =
                    (xs[tg_glob + 4] + selu_f(contrib)) * RES_SC;
            }
        }
        __syncthreads();
    }
}

// ---------------------------------------------------------------------------
// Head
// ---------------------------------------------------------------------------
__global__ __launch_bounds__(256)
void head_kernel(const float* __restrict__ x, const float* __restrict__ wh,
                 const float* __restrict__ bh, float* __restrict__ out) {
    const int n = blockIdx.x, b = blockIdx.y, tid = threadIdx.x;
    const float4* xr = reinterpret_cast<const float4*>(x + (size_t)b * 64000);
    const float4* wr = reinterpret_cast<const float4*>(wh + (size_t)n * 64000);
    float sum = 0.0f;
    for (int i = tid; i < 16000; i += 256) {
        float4 a = xr[i], w = wr[i];
        sum += a.x * w.x + a.y * w.y + a.z * w.z + a.w * w.w;
    }
#pragma unroll
    for (int off = 16; off; off >>= 1)
        sum += __shfl_down_sync(0xffffffffu, sum, off);
    __shared__ float ps[8];
    if ((tid & 31) == 0) ps[tid >> 5] = sum;
    __syncthreads();
    if (tid < 8) {
        sum = ps[tid];
#pragma unroll
        for (int off = 4; off; off >>= 1)
            sum += __shfl_down_sync(0xffu, sum, off);
        if (tid == 0) out[b * 40 + n] = sum + bh[n];
    }
}

// ---------------------------------------------------------------------------
extern "C" void kernel_launch(void* const* d_in, const int* in_sizes, int n_in,
                              void* d_out, int out_size) {
    const float* x     = (const float*)d_in[0];
    const float* wq    = (const float*)d_in[2];  // (2,128,21,9)
    const float* wk    = (const float*)d_in[3];  // (2,16384,1,9)
    const float* wv    = (const float*)d_in[4];  // (2,16384,1,9)
    const float* wproj = (const float*)d_in[5];  // (2,128,128)
    const float* whead = (const float*)d_in[6];  // (40,64000)
    const float* bhead = (const float*)d_in[7];  // (40,)
    float* out = (float*)d_out;

    float *gx = nullptr, *gq = nullptr;
    cudaGetSymbolAddress((void**)&gx, g_x);
    cudaGetSymbolAddress((void**)&gq, g_q);

    cudaFuncSetAttribute(layer_mma_kernel,
                         cudaFuncAttributeMaxDynamicSharedMemorySize, SMEM_BYTES);

    dim3 qg(8, 2, 8);
    dim3 lg(128, 8);
    dim3 hg(40, 8);

    q_kernel<<<qg, 128>>>(x, wq, gq);
    layer_mma_kernel<<<lg, 256, SMEM_BYTES>>>(x, gq, wk, wv, wproj, gx);
    q_kernel<<<qg, 128>>>(gx, wq + 24192, gq);
    layer_mma_kernel<<<lg, 256, SMEM_BYTES>>>(gx, gq, wk + 147456, wv + 147456,
                                              wproj + 16384, gx);
    head_kernel<<<hg, 256>>>(gx, whead, bhead, out);
}